// round 1
// baseline (speedup 1.0000x reference)
#include <cuda_runtime.h>
#include <cuda_bf16.h>
#include <cstdint>

// ---------------------------------------------------------------------------
// RingAttention: X -> Q,K,V proj -> block-local-max ring attention -> O proj
// B=1, S=4096, HIDDEN=1024, H=16, D=64, BLOCK=1024 (4 kv blocks)
// ---------------------------------------------------------------------------

#define S_LEN   4096
#define HID     1024
#define HEADS   16
#define HDIM    64
#define NBLK    4
#define KVBLK   1024

// Scratch (allocation-free rule: __device__ globals)
__device__ float g_Q[HEADS * S_LEN * HDIM];   // [h][s][d]
__device__ float g_K[HEADS * S_LEN * HDIM];
__device__ float g_V[HEADS * S_LEN * HDIM];
__device__ float g_A[S_LEN * HID];            // attention out [s][h*64+d]

// ---------------------------------------------------------------------------
// SGEMM: C[4096,1024] = A[4096,1024] @ B[1024,1024], fp32
// 128x128 tile, BK=8, 256 threads, 8x8 per thread.
// headmajor=1: write C to [h][m][d] layout (h=n/64, d=n%64)
// ---------------------------------------------------------------------------
__global__ __launch_bounds__(256) void sgemm_k(const float* __restrict__ A,
                                               const float* __restrict__ B,
                                               float* __restrict__ C,
                                               int headmajor)
{
    const int M = S_LEN, N = HID, K = HID;
    __shared__ float As[8][128];
    __shared__ float Bs[8][128];

    int m0 = blockIdx.y * 128;
    int n0 = blockIdx.x * 128;
    int tid = threadIdx.x;
    int tx = tid & 15;        // 0..15 (n dir)
    int ty = tid >> 4;        // 0..15 (m dir)

    float acc[8][8];
#pragma unroll
    for (int i = 0; i < 8; i++)
#pragma unroll
        for (int j = 0; j < 8; j++) acc[i][j] = 0.f;

    for (int k0 = 0; k0 < K; k0 += 8) {
        // load A tile 128x8 -> As[k][m]
#pragma unroll
        for (int l = 0; l < 4; l++) {
            int e = tid + l * 256;
            int r = e >> 3, kk = e & 7;
            As[kk][r] = A[(size_t)(m0 + r) * K + (k0 + kk)];
        }
        // load B tile 8x128 -> Bs[k][n]
#pragma unroll
        for (int l = 0; l < 4; l++) {
            int e = tid + l * 256;
            int kk = e >> 7, c = e & 127;
            Bs[kk][c] = B[(size_t)(k0 + kk) * N + (n0 + c)];
        }
        __syncthreads();
#pragma unroll
        for (int kk = 0; kk < 8; kk++) {
            float a[8], b[8];
#pragma unroll
            for (int i = 0; i < 8; i++) a[i] = As[kk][ty * 8 + i];
#pragma unroll
            for (int j = 0; j < 8; j++) b[j] = Bs[kk][tx * 8 + j];
#pragma unroll
            for (int i = 0; i < 8; i++)
#pragma unroll
                for (int j = 0; j < 8; j++)
                    acc[i][j] = fmaf(a[i], b[j], acc[i][j]);
        }
        __syncthreads();
    }

    if (headmajor) {
#pragma unroll
        for (int i = 0; i < 8; i++) {
            int m = m0 + ty * 8 + i;
#pragma unroll
            for (int j = 0; j < 8; j++) {
                int n = n0 + tx * 8 + j;
                int h = n >> 6, d = n & 63;
                C[((size_t)h * S_LEN + m) * HDIM + d] = acc[i][j];
            }
        }
    } else {
#pragma unroll
        for (int i = 0; i < 8; i++) {
            int m = m0 + ty * 8 + i;
#pragma unroll
            for (int j = 0; j < 8; j++) {
                int n = n0 + tx * 8 + j;
                C[(size_t)m * N + n] = acc[i][j];
            }
        }
    }
}

// ---------------------------------------------------------------------------
// fast exp via 2^f polynomial (avoids MUFU.EX2 throughput wall)
// x <= 0 always (score - blockmax)
// ---------------------------------------------------------------------------
__device__ __forceinline__ float fexp(float x)
{
    float y = fmaxf(x * 1.4426950408889634f, -110.0f);
    float n = rintf(y);
    float f = y - n;
    float p = 1.3333558146428443e-3f;
    p = fmaf(p, f, 9.618129842071803e-3f);
    p = fmaf(p, f, 5.550410866482158e-2f);
    p = fmaf(p, f, 2.402265069591007e-1f);
    p = fmaf(p, f, 6.931471805599453e-1f);
    p = fmaf(p, f, 1.0f);
    return p * __int_as_float(((int)n + 127) << 23);
}

// ---------------------------------------------------------------------------
// Attention kernel: CTA = 32 queries x 1 head. Full 32x1024 score block in
// SMEM (single QK^T pass per KV block, per-block local max, additive num/den
// accumulation across blocks -> matches reference "ring" semantics exactly).
// ---------------------------------------------------------------------------
#define ATQ  32
#define SP   1025      // score pitch (conflict-free column scans)
#define KP   129       // K^T chunk pitch
#define VP   68        // V chunk pitch
#define KVBUF 8704     // max(64*129, 128*68)

__global__ __launch_bounds__(256) void attn_k(const float* __restrict__ Qg,
                                              const float* __restrict__ Kg,
                                              const float* __restrict__ Vg,
                                              float* __restrict__ Aout)
{
    extern __shared__ float sm[];
    float* Ssc = sm;                       // [32][SP]
    float* KVb = Ssc + ATQ * SP;           // K^T / V chunk + reductions
    float* Qs  = KVb + KVBUF;              // [32][64]
    float* dsh = Qs + ATQ * HDIM;          // [32] den accum

    const int h  = blockIdx.y;
    const int q0 = blockIdx.x * ATQ;
    const int tid = threadIdx.x;

    const float* Qh = Qg + ((size_t)h * S_LEN + q0) * HDIM;
    const float* Kh = Kg + (size_t)h * S_LEN * HDIM;
    const float* Vh = Vg + (size_t)h * S_LEN * HDIM;

    // load Q tile (coalesced), init den
#pragma unroll
    for (int l = 0; l < 8; l++) {
        int e = tid + l * 256;
        Qs[e] = Qh[e];
    }
    if (tid < ATQ) dsh[tid] = 0.f;

    // thread roles
    const int qg  = tid >> 5;      // QK: q-group (4 rows)
    const int kt  = tid & 31;      // QK: key lane
    const int half = tid >> 7;     // PV: k-split half
    const int u   = tid & 127;
    const int dg  = u & 15;        // PV: d-group (4 cols)
    const int qg2 = u >> 4;        // PV: q-group (4 rows)
    const int qs  = tid & 31;      // exp phase: query row
    const int s8  = tid >> 5;      // exp phase: segment

    float num[4][4];
#pragma unroll
    for (int i = 0; i < 4; i++)
#pragma unroll
        for (int j = 0; j < 4; j++) num[i][j] = 0.f;

    __syncthreads();

    for (int blk = 0; blk < NBLK; blk++) {
        const float* Kb = Kh + (size_t)blk * KVBLK * HDIM;
        const float* Vb = Vh + (size_t)blk * KVBLK * HDIM;

        // ---------- QK^T -> Ssc (scaled) ----------
        for (int c = 0; c < 8; c++) {
            __syncthreads();
            // load K chunk transposed: KsT[d][kk], pitch KP
#pragma unroll 8
            for (int l = 0; l < 32; l++) {
                int e = tid + l * 256;
                int kk = e >> 6, d = e & 63;
                KVb[d * KP + kk] = Kb[(size_t)(c * 128 + kk) * HDIM + d];
            }
            __syncthreads();

            float acc[4][4];
#pragma unroll
            for (int i = 0; i < 4; i++)
#pragma unroll
                for (int j = 0; j < 4; j++) acc[i][j] = 0.f;

#pragma unroll 4
            for (int d = 0; d < 64; d++) {
                float qv[4], kv[4];
#pragma unroll
                for (int i = 0; i < 4; i++) qv[i] = Qs[(qg * 4 + i) * HDIM + d];
#pragma unroll
                for (int j = 0; j < 4; j++) kv[j] = KVb[d * KP + kt + 32 * j];
#pragma unroll
                for (int i = 0; i < 4; i++)
#pragma unroll
                    for (int j = 0; j < 4; j++)
                        acc[i][j] = fmaf(qv[i], kv[j], acc[i][j]);
            }
#pragma unroll
            for (int i = 0; i < 4; i++)
#pragma unroll
                for (int j = 0; j < 4; j++)
                    Ssc[(qg * 4 + i) * SP + c * 128 + kt + 32 * j] = acc[i][j] * 0.125f;
        }
        __syncthreads();

        // ---------- block-local max ----------
        {
            float* row = Ssc + qs * SP + s8 * 128;
            float m = -1e30f;
#pragma unroll 8
            for (int i = 0; i < 128; i++) m = fmaxf(m, row[i]);
            KVb[tid] = m;   // partials
        }
        __syncthreads();
        if (tid < ATQ) {
            float m = KVb[tid];
#pragma unroll
            for (int s = 1; s < 8; s++) m = fmaxf(m, KVb[tid + 32 * s]);
            KVb[256 + tid] = m;   // final row max
        }
        __syncthreads();

        // ---------- exp + den ----------
        {
            float m = KVb[256 + qs];
            float* row = Ssc + qs * SP + s8 * 128;
            float sum = 0.f;
#pragma unroll 4
            for (int i = 0; i < 128; i++) {
                float e = fexp(row[i] - m);
                row[i] = e;
                sum += e;
            }
            KVb[512 + tid] = sum;
        }
        __syncthreads();
        if (tid < ATQ) {
            float s = 0.f;
#pragma unroll
            for (int j = 0; j < 8; j++) s += KVb[512 + tid + 32 * j];
            dsh[tid] += s;
        }
        // (PV loop's leading __syncthreads covers visibility of exp writes)

        // ---------- PV: num += E @ V ----------
        for (int c = 0; c < 8; c++) {
            __syncthreads();
#pragma unroll 8
            for (int l = 0; l < 32; l++) {
                int e = tid + l * 256;
                int kk = e >> 6, d = e & 63;
                KVb[kk * VP + d] = Vb[(size_t)(c * 128 + kk) * HDIM + d];
            }
            __syncthreads();

            const int kbase = c * 128 + half * 64;
            const float* Srow = Ssc + kbase;
            const float* Vrow = KVb + (half * 64) * VP + dg * 4;
#pragma unroll 4
            for (int kk = 0; kk < 64; kk++) {
                float sv[4], vv[4];
#pragma unroll
                for (int i = 0; i < 4; i++) sv[i] = Srow[(qg2 * 4 + i) * SP + kk];
#pragma unroll
                for (int j = 0; j < 4; j++) vv[j] = Vrow[kk * VP + j];
#pragma unroll
                for (int i = 0; i < 4; i++)
#pragma unroll
                    for (int j = 0; j < 4; j++)
                        num[i][j] = fmaf(sv[i], vv[j], num[i][j]);
            }
        }
    }

    __syncthreads();
    // reduce the two k-split halves through SMEM (Ssc is free now)
    if (half == 1) {
#pragma unroll
        for (int i = 0; i < 4; i++)
#pragma unroll
            for (int j = 0; j < 4; j++)
                Ssc[u * 16 + i * 4 + j] = num[i][j];
    }
    __syncthreads();
    if (half == 0) {
#pragma unroll
        for (int i = 0; i < 4; i++) {
            float inv = 1.0f / dsh[qg2 * 4 + i];
#pragma unroll
            for (int j = 0; j < 4; j++) {
                float v = num[i][j] + Ssc[u * 16 + i * 4 + j];
                Aout[(size_t)(q0 + qg2 * 4 + i) * HID + h * HDIM + dg * 4 + j] = v * inv;
            }
        }
    }
}

// ---------------------------------------------------------------------------
// launch
// ---------------------------------------------------------------------------
extern "C" void kernel_launch(void* const* d_in, const int* in_sizes, int n_in,
                              void* d_out, int out_size)
{
    const float* x   = (const float*)d_in[0];
    const float* w_q = (const float*)d_in[1];
    const float* w_k = (const float*)d_in[2];
    const float* w_v = (const float*)d_in[3];
    const float* w_o = (const float*)d_in[4];
    float* out = (float*)d_out;

    float *Qp, *Kp, *Vp, *Ap;
    cudaGetSymbolAddress((void**)&Qp, g_Q);
    cudaGetSymbolAddress((void**)&Kp, g_K);
    cudaGetSymbolAddress((void**)&Vp, g_V);
    cudaGetSymbolAddress((void**)&Ap, g_A);

    // attention kernel needs >48KB dynamic smem
    const int smem_bytes = (ATQ * SP + KVBUF + ATQ * HDIM + ATQ) * sizeof(float);
    cudaFuncSetAttribute(attn_k, cudaFuncAttributeMaxDynamicSharedMemorySize, smem_bytes);

    dim3 gemm_grid(HID / 128, S_LEN / 128);

    // Q/K/V projections (head-major outputs)
    sgemm_k<<<gemm_grid, 256>>>(x, w_q, Qp, 1);
    sgemm_k<<<gemm_grid, 256>>>(x, w_k, Kp, 1);
    sgemm_k<<<gemm_grid, 256>>>(x, w_v, Vp, 1);

    // attention
    dim3 attn_grid(S_LEN / ATQ, HEADS);
    attn_k<<<attn_grid, 256, smem_bytes>>>(Qp, Kp, Vp, Ap);

    // O projection -> d_out
    sgemm_k<<<gemm_grid, 256>>>(Ap, w_o, out, 0);
}

// round 3
// speedup vs baseline: 1.2366x; 1.2366x over previous
#include <cuda_runtime.h>
#include <cuda_bf16.h>
#include <cstdint>

// ---------------------------------------------------------------------------
// RingAttention: X -> Q,K,V proj (mma.sync 3xbf16) -> ring attention (fp32 SIMT)
//                -> O proj (mma.sync 3xbf16)
// B=1, S=4096, HIDDEN=1024, H=16, D=64, BLOCK=1024 (4 kv blocks)
// NOTE: toolchain targets compute_103 (no 'a' feature) -> tcgen05 unavailable;
//       use mma.sync (HMMA) + cp.async + ldmatrix, all baseline sm_80+.
// ---------------------------------------------------------------------------

#define S_LEN   4096
#define HID     1024
#define HEADS   16
#define HDIM    64
#define NBLK    4
#define KVBLK   1024

// fp32 scratch
__device__ float g_Q[HEADS * S_LEN * HDIM];
__device__ float g_K[HEADS * S_LEN * HDIM];
__device__ float g_V[HEADS * S_LEN * HDIM];
__device__ float g_A[S_LEN * HID];

// bf16 hi/lo split scratch
__device__ __nv_bfloat16 g_Xhi[S_LEN * HID];
__device__ __nv_bfloat16 g_Xlo[S_LEN * HID];
__device__ __nv_bfloat16 g_Ahi[S_LEN * HID];
__device__ __nv_bfloat16 g_Alo[S_LEN * HID];
__device__ __nv_bfloat16 g_Wh[4][HID * HID];   // transposed [n][k]
__device__ __nv_bfloat16 g_Wl[4][HID * HID];

// ---------------------------------------------------------------------------
// PTX helpers (baseline ISA only)
// ---------------------------------------------------------------------------
__device__ __forceinline__ uint32_t smem_u32(const void* p) {
    uint32_t a;
    asm("{ .reg .u64 t; cvta.to.shared.u64 t, %1; cvt.u32.u64 %0, t; }" : "=r"(a) : "l"(p));
    return a;
}

#define CP_ASYNC16(dst, src) \
    asm volatile("cp.async.cg.shared.global [%0], [%1], 16;" :: "r"(dst), "l"(src))
#define CP_COMMIT() asm volatile("cp.async.commit_group;" ::: "memory")
#define CP_WAIT0()  asm volatile("cp.async.wait_group 0;" ::: "memory")
#define CP_WAIT1()  asm volatile("cp.async.wait_group 1;" ::: "memory")

#define LDSM_X4(r0, r1, r2, r3, addr) \
    asm volatile("ldmatrix.sync.aligned.m8n8.x4.shared.b16 {%0,%1,%2,%3}, [%4];" \
                 : "=r"(r0), "=r"(r1), "=r"(r2), "=r"(r3) : "r"(addr))

#define MMA16816(d, a, b) \
    asm volatile("mma.sync.aligned.m16n8k16.row.col.f32.bf16.bf16.f32 " \
                 "{%0,%1,%2,%3}, {%4,%5,%6,%7}, {%8,%9}, {%0,%1,%2,%3};" \
                 : "+f"((d)[0]), "+f"((d)[1]), "+f"((d)[2]), "+f"((d)[3]) \
                 : "r"((a)[0]), "r"((a)[1]), "r"((a)[2]), "r"((a)[3]), \
                   "r"((b)[0]), "r"((b)[1]))

// ---------------------------------------------------------------------------
// hi/lo bf16 split conversion
// ---------------------------------------------------------------------------
__global__ __launch_bounds__(256) void convhl_k(const float* __restrict__ X,
                                                __nv_bfloat16* __restrict__ H,
                                                __nv_bfloat16* __restrict__ L)
{
    int i = (blockIdx.x * 256 + threadIdx.x) * 4;
    float4 v = *reinterpret_cast<const float4*>(X + i);
    __nv_bfloat16 h[4], l[4];
    float f[4] = {v.x, v.y, v.z, v.w};
#pragma unroll
    for (int j = 0; j < 4; j++) {
        h[j] = __float2bfloat16(f[j]);
        l[j] = __float2bfloat16(f[j] - __bfloat162float(h[j]));
    }
    *reinterpret_cast<uint2*>(H + i) = *reinterpret_cast<uint2*>(h);
    *reinterpret_cast<uint2*>(L + i) = *reinterpret_cast<uint2*>(l);
}

// transpose + hi/lo split: W[K][N] f32 -> Ht/Lt[N][K] bf16
__global__ __launch_bounds__(256) void convwt_k(const float* __restrict__ W,
                                                __nv_bfloat16* __restrict__ Ht,
                                                __nv_bfloat16* __restrict__ Lt)
{
    __shared__ float t[32][33];
    int n0 = blockIdx.x * 32, k0 = blockIdx.y * 32;
    int tx = threadIdx.x & 31, ty = threadIdx.x >> 5;
#pragma unroll
    for (int s = 0; s < 32; s += 8)
        t[ty + s][tx] = W[(size_t)(k0 + ty + s) * HID + n0 + tx];
    __syncthreads();
#pragma unroll
    for (int s = 0; s < 32; s += 8) {
        float v = t[tx][ty + s];
        __nv_bfloat16 h = __float2bfloat16(v);
        __nv_bfloat16 l = __float2bfloat16(v - __bfloat162float(h));
        size_t o = (size_t)(n0 + ty + s) * HID + k0 + tx;
        Ht[o] = h;
        Lt[o] = l;
    }
}

// ---------------------------------------------------------------------------
// HMMA 3xbf16 GEMM: C[4096,1024] = A @ Bt^T
//   A: Ah+Al bf16 row-major [m][k];  B: Bh+Bl bf16 row-major [n][k]
//   C = Ah*Bh + Ah*Bl + Al*Bh  (fp32 accum)
// CTA: 128x128 tile, 256 thr (8 warps, each 64x32), K-chunk 32, cp.async
// double buffer. SMEM rows pitch 80B (conflict-free ldmatrix).
// ---------------------------------------------------------------------------
#define GKC   32                       // K per chunk
#define GNC   (HID / GKC)              // 32 chunks
#define ARRB  (128 * 80)               // bytes per operand tile (pitch 80B)
#define BUFB  (4 * ARRB)               // 40960 B per buffer
#define EPIP  132                      // epilogue fp32 pitch

__global__ __launch_bounds__(256) void gemmmma_k(const __nv_bfloat16* __restrict__ Ah,
                                                 const __nv_bfloat16* __restrict__ Al,
                                                 const __nv_bfloat16* __restrict__ Bh,
                                                 const __nv_bfloat16* __restrict__ Bl,
                                                 float* __restrict__ C,
                                                 int headmajor)
{
    extern __shared__ char dsm[];
    const uint32_t sbase = smem_u32(dsm);

    const int tid  = threadIdx.x;
    const int wid  = tid >> 5;
    const int lane = tid & 31;
    const int m0 = blockIdx.y * 128;
    const int n0 = blockIdx.x * 128;
    const int m0w = (wid & 1) * 64;    // warp tile origin in CTA
    const int n0w = (wid >> 1) * 32;

    float acc[4][4][4];
#pragma unroll
    for (int i = 0; i < 4; i++)
#pragma unroll
        for (int j = 0; j < 4; j++)
#pragma unroll
            for (int r = 0; r < 4; r++) acc[i][j][r] = 0.f;

    auto load_chunk = [&](int c, int b) {
        const int koff = c * GKC;
        const uint32_t dst0 = sbase + b * BUFB;
#pragma unroll
        for (int l = 0; l < 8; l++) {
            int e = tid + l * 256;               // 0..2047
            int arr = e >> 9;                    // 0..3
            int r = (e >> 2) & 127;
            int q = e & 3;
            const __nv_bfloat16* G = (arr == 0) ? Ah : (arr == 1) ? Al
                                   : (arr == 2) ? Bh : Bl;
            int t0 = (arr < 2) ? m0 : n0;
            const __nv_bfloat16* src = G + (size_t)(t0 + r) * HID + koff + q * 8;
            CP_ASYNC16(dst0 + arr * ARRB + r * 80 + q * 16, src);
        }
    };

    load_chunk(0, 0);
    CP_COMMIT();

    for (int c = 0; c < GNC; c++) {
        const int b = c & 1;
        if (c + 1 < GNC) { load_chunk(c + 1, (c + 1) & 1); CP_COMMIT(); CP_WAIT1(); }
        else             { CP_WAIT0(); }
        __syncthreads();

        const uint32_t bufb = sbase + b * BUFB;
        const int arow = (lane & 15);
        const int acolb = ((lane >> 4) * 8) * 2;
        const int brow = ((lane >> 4) << 3) + (lane & 7);
        const int bcolb = (((lane >> 3) & 1) * 8) * 2;

#pragma unroll
        for (int kk = 0; kk < 2; kk++) {
            uint32_t ah[4][4], al[4][4], bh[4][2], bl[4][2];
            const int kb = kk * 32;   // 16 bf16 * 2B
#pragma unroll
            for (int i = 0; i < 4; i++) {
                uint32_t ad = bufb + (m0w + i * 16 + arow) * 80 + acolb + kb;
                LDSM_X4(ah[i][0], ah[i][1], ah[i][2], ah[i][3], ad);
                LDSM_X4(al[i][0], al[i][1], al[i][2], al[i][3], ad + ARRB);
            }
            {
                uint32_t bd = bufb + 2 * ARRB + (n0w + brow) * 80 + bcolb + kb;
                uint32_t r0, r1, r2, r3;
                LDSM_X4(r0, r1, r2, r3, bd);
                bh[0][0] = r0; bh[0][1] = r1; bh[1][0] = r2; bh[1][1] = r3;
                LDSM_X4(r0, r1, r2, r3, bd + 16 * 80);
                bh[2][0] = r0; bh[2][1] = r1; bh[3][0] = r2; bh[3][1] = r3;
                LDSM_X4(r0, r1, r2, r3, bd + ARRB);
                bl[0][0] = r0; bl[0][1] = r1; bl[1][0] = r2; bl[1][1] = r3;
                LDSM_X4(r0, r1, r2, r3, bd + ARRB + 16 * 80);
                bl[2][0] = r0; bl[2][1] = r1; bl[3][0] = r2; bl[3][1] = r3;
            }
#pragma unroll
            for (int i = 0; i < 4; i++)
#pragma unroll
                for (int j = 0; j < 4; j++) {
                    MMA16816(acc[i][j], ah[i], bh[j]);
                    MMA16816(acc[i][j], ah[i], bl[j]);
                    MMA16816(acc[i][j], al[i], bh[j]);
                }
        }
        __syncthreads();
    }

    // epilogue: frags -> SMEM (fp32, pitch EPIP) -> coalesced global
    float* fsm = reinterpret_cast<float*>(dsm);
    const int r0w = m0w + (lane >> 2);
    const int c0w = n0w + (lane & 3) * 2;
#pragma unroll
    for (int i = 0; i < 4; i++)
#pragma unroll
        for (int j = 0; j < 4; j++) {
            int r = r0w + i * 16, cc = c0w + j * 8;
            fsm[r * EPIP + cc]           = acc[i][j][0];
            fsm[r * EPIP + cc + 1]       = acc[i][j][1];
            fsm[(r + 8) * EPIP + cc]     = acc[i][j][2];
            fsm[(r + 8) * EPIP + cc + 1] = acc[i][j][3];
        }
    __syncthreads();
#pragma unroll
    for (int l = 0; l < 64; l++) {
        int e = tid + l * 256;
        int r = e >> 7, cc = e & 127;
        float v = fsm[r * EPIP + cc];
        if (headmajor) {
            int n = n0 + cc;
            C[((size_t)(n >> 6) * S_LEN + m0 + r) * HDIM + (n & 63)] = v;
        } else {
            C[(size_t)(m0 + r) * HID + n0 + cc] = v;
        }
    }
}

// ---------------------------------------------------------------------------
// fast exp
// ---------------------------------------------------------------------------
__device__ __forceinline__ float fexp(float x)
{
    float y = fmaxf(x * 1.4426950408889634f, -110.0f);
    float n = rintf(y);
    float f = y - n;
    float p = 1.3333558146428443e-3f;
    p = fmaf(p, f, 9.618129842071803e-3f);
    p = fmaf(p, f, 5.550410866482158e-2f);
    p = fmaf(p, f, 2.402265069591007e-1f);
    p = fmaf(p, f, 6.931471805599453e-1f);
    p = fmaf(p, f, 1.0f);
    return p * __int_as_float(((int)n + 127) << 23);
}

// ---------------------------------------------------------------------------
// Attention kernel (round-1 version, unchanged — fp32 SIMT, ring semantics)
// ---------------------------------------------------------------------------
#define ATQ  32
#define SP   1025
#define KP   129
#define VP   68
#define KVBUF 8704

__global__ __launch_bounds__(256) void attn_k(const float* __restrict__ Qg,
                                              const float* __restrict__ Kg,
                                              const float* __restrict__ Vg,
                                              float* __restrict__ Aout)
{
    extern __shared__ float sm[];
    float* Ssc = sm;
    float* KVb = Ssc + ATQ * SP;
    float* Qs  = KVb + KVBUF;
    float* dsh = Qs + ATQ * HDIM;

    const int h  = blockIdx.y;
    const int q0 = blockIdx.x * ATQ;
    const int tid = threadIdx.x;

    const float* Qh = Qg + ((size_t)h * S_LEN + q0) * HDIM;
    const float* Kh = Kg + (size_t)h * S_LEN * HDIM;
    const float* Vh = Vg + (size_t)h * S_LEN * HDIM;

#pragma unroll
    for (int l = 0; l < 8; l++) {
        int e = tid + l * 256;
        Qs[e] = Qh[e];
    }
    if (tid < ATQ) dsh[tid] = 0.f;

    const int qg  = tid >> 5;
    const int kt  = tid & 31;
    const int half = tid >> 7;
    const int u   = tid & 127;
    const int dg  = u & 15;
    const int qg2 = u >> 4;
    const int qs  = tid & 31;
    const int s8  = tid >> 5;

    float num[4][4];
#pragma unroll
    for (int i = 0; i < 4; i++)
#pragma unroll
        for (int j = 0; j < 4; j++) num[i][j] = 0.f;

    __syncthreads();

    for (int blk = 0; blk < NBLK; blk++) {
        const float* Kb = Kh + (size_t)blk * KVBLK * HDIM;
        const float* Vb = Vh + (size_t)blk * KVBLK * HDIM;

        for (int c = 0; c < 8; c++) {
            __syncthreads();
#pragma unroll 8
            for (int l = 0; l < 32; l++) {
                int e = tid + l * 256;
                int kk = e >> 6, d = e & 63;
                KVb[d * KP + kk] = Kb[(size_t)(c * 128 + kk) * HDIM + d];
            }
            __syncthreads();

            float acc[4][4];
#pragma unroll
            for (int i = 0; i < 4; i++)
#pragma unroll
                for (int j = 0; j < 4; j++) acc[i][j] = 0.f;

#pragma unroll 4
            for (int d = 0; d < 64; d++) {
                float qv[4], kv[4];
#pragma unroll
                for (int i = 0; i < 4; i++) qv[i] = Qs[(qg * 4 + i) * HDIM + d];
#pragma unroll
                for (int j = 0; j < 4; j++) kv[j] = KVb[d * KP + kt + 32 * j];
#pragma unroll
                for (int i = 0; i < 4; i++)
#pragma unroll
                    for (int j = 0; j < 4; j++)
                        acc[i][j] = fmaf(qv[i], kv[j], acc[i][j]);
            }
#pragma unroll
            for (int i = 0; i < 4; i++)
#pragma unroll
                for (int j = 0; j < 4; j++)
                    Ssc[(qg * 4 + i) * SP + c * 128 + kt + 32 * j] = acc[i][j] * 0.125f;
        }
        __syncthreads();

        {
            float* row = Ssc + qs * SP + s8 * 128;
            float m = -1e30f;
#pragma unroll 8
            for (int i = 0; i < 128; i++) m = fmaxf(m, row[i]);
            KVb[tid] = m;
        }
        __syncthreads();
        if (tid < ATQ) {
            float m = KVb[tid];
#pragma unroll
            for (int s = 1; s < 8; s++) m = fmaxf(m, KVb[tid + 32 * s]);
            KVb[256 + tid] = m;
        }
        __syncthreads();

        {
            float m = KVb[256 + qs];
            float* row = Ssc + qs * SP + s8 * 128;
            float sum = 0.f;
#pragma unroll 4
            for (int i = 0; i < 128; i++) {
                float e = fexp(row[i] - m);
                row[i] = e;
                sum += e;
            }
            KVb[512 + tid] = sum;
        }
        __syncthreads();
        if (tid < ATQ) {
            float s = 0.f;
#pragma unroll
            for (int j = 0; j < 8; j++) s += KVb[512 + tid + 32 * j];
            dsh[tid] += s;
        }

        for (int c = 0; c < 8; c++) {
            __syncthreads();
#pragma unroll 8
            for (int l = 0; l < 32; l++) {
                int e = tid + l * 256;
                int kk = e >> 6, d = e & 63;
                KVb[kk * VP + d] = Vb[(size_t)(c * 128 + kk) * HDIM + d];
            }
            __syncthreads();

            const int kbase = c * 128 + half * 64;
            const float* Srow = Ssc + kbase;
            const float* Vrow = KVb + (half * 64) * VP + dg * 4;
#pragma unroll 4
            for (int kk = 0; kk < 64; kk++) {
                float sv[4], vv[4];
#pragma unroll
                for (int i = 0; i < 4; i++) sv[i] = Srow[(qg2 * 4 + i) * SP + kk];
#pragma unroll
                for (int j = 0; j < 4; j++) vv[j] = Vrow[kk * VP + j];
#pragma unroll
                for (int i = 0; i < 4; i++)
#pragma unroll
                    for (int j = 0; j < 4; j++)
                        num[i][j] = fmaf(sv[i], vv[j], num[i][j]);
            }
        }
    }

    __syncthreads();
    if (half == 1) {
#pragma unroll
        for (int i = 0; i < 4; i++)
#pragma unroll
            for (int j = 0; j < 4; j++)
                Ssc[u * 16 + i * 4 + j] = num[i][j];
    }
    __syncthreads();
    if (half == 0) {
#pragma unroll
        for (int i = 0; i < 4; i++) {
            float inv = 1.0f / dsh[qg2 * 4 + i];
#pragma unroll
            for (int j = 0; j < 4; j++) {
                float v = num[i][j] + Ssc[u * 16 + i * 4 + j];
                Aout[(size_t)(q0 + qg2 * 4 + i) * HID + h * HDIM + dg * 4 + j] = v * inv;
            }
        }
    }
}

// ---------------------------------------------------------------------------
// launch
// ---------------------------------------------------------------------------
extern "C" void kernel_launch(void* const* d_in, const int* in_sizes, int n_in,
                              void* d_out, int out_size)
{
    const float* x   = (const float*)d_in[0];
    const float* w_q = (const float*)d_in[1];
    const float* w_k = (const float*)d_in[2];
    const float* w_v = (const float*)d_in[3];
    const float* w_o = (const float*)d_in[4];
    float* out = (float*)d_out;

    float *Qp, *Kp, *Vp, *Ap;
    cudaGetSymbolAddress((void**)&Qp, g_Q);
    cudaGetSymbolAddress((void**)&Kp, g_K);
    cudaGetSymbolAddress((void**)&Vp, g_V);
    cudaGetSymbolAddress((void**)&Ap, g_A);

    __nv_bfloat16 *Xh, *Xl, *Ahp, *Alp, *Wh, *Wl;
    cudaGetSymbolAddress((void**)&Xh, g_Xhi);
    cudaGetSymbolAddress((void**)&Xl, g_Xlo);
    cudaGetSymbolAddress((void**)&Ahp, g_Ahi);
    cudaGetSymbolAddress((void**)&Alp, g_Alo);
    cudaGetSymbolAddress((void**)&Wh, g_Wh);
    cudaGetSymbolAddress((void**)&Wl, g_Wl);

    const int attn_smem = (ATQ * SP + KVBUF + ATQ * HDIM + ATQ) * sizeof(float);
    cudaFuncSetAttribute(attn_k, cudaFuncAttributeMaxDynamicSharedMemorySize, attn_smem);

    const int gemm_smem = 2 * BUFB;   // 81920 B (also covers 128*EPIP*4 epilogue)
    cudaFuncSetAttribute(gemmmma_k, cudaFuncAttributeMaxDynamicSharedMemorySize, gemm_smem);

    // hi/lo conversions
    convhl_k<<<(S_LEN * HID) / 1024, 256>>>(x, Xh, Xl);
    dim3 wt_grid(HID / 32, HID / 32);
    const float* ws[4] = {w_q, w_k, w_v, w_o};
    for (int i = 0; i < 4; i++)
        convwt_k<<<wt_grid, 256>>>(ws[i], Wh + (size_t)i * HID * HID, Wl + (size_t)i * HID * HID);

    dim3 gg(HID / 128, S_LEN / 128);
    gemmmma_k<<<gg, 256, gemm_smem>>>(Xh, Xl, Wh + 0 * (size_t)HID * HID, Wl + 0 * (size_t)HID * HID, Qp, 1);
    gemmmma_k<<<gg, 256, gemm_smem>>>(Xh, Xl, Wh + 1 * (size_t)HID * HID, Wl + 1 * (size_t)HID * HID, Kp, 1);
    gemmmma_k<<<gg, 256, gemm_smem>>>(Xh, Xl, Wh + 2 * (size_t)HID * HID, Wl + 2 * (size_t)HID * HID, Vp, 1);

    dim3 attn_grid(S_LEN / ATQ, HEADS);
    attn_k<<<attn_grid, 256, attn_smem>>>(Qp, Kp, Vp, Ap);

    convhl_k<<<(S_LEN * HID) / 1024, 256>>>(Ap, Ahp, Alp);
    gemmmma_k<<<gg, 256, gemm_smem>>>(Ahp, Alp, Wh + 3 * (size_t)HID * HID, Wl + 3 * (size_t)HID * HID, out, 0);
}